// round 1
// baseline (speedup 1.0000x reference)
#include <cuda_runtime.h>
#include <cuda_bf16.h>
#include <cstdint>

#define NODES   68000
#define BATCH   4
#define NPROT   17000
#define CDIM    128

// ---------------- scratch (allocation-free: __device__ globals) ----------------
__device__ __align__(16) int   g_deg[NODES];
__device__ __align__(16) float g_dinv[NODES];
__device__ __align__(16) float g_h[NODES * CDIM];      // h = in @ W (pre-aggregation)
__device__ __align__(16) float g_agg[NODES * CDIM];    // aggregation accumulator
__device__ __align__(16) float g_in[NODES * CDIM];     // next-layer input (relu output)
__device__ __align__(16) float g_s[NODES * CDIM];      // residual sum h1+h2+h3
__device__ __align__(16) float g_pooled[BATCH * CDIM];

// ---------------- zero init (deg + pooled) ----------------
__global__ void zero_kernel(int* deg, float* pooled, int n_deg, int n_pool) {
    int i = blockIdx.x * blockDim.x + threadIdx.x;
    int stride = gridDim.x * blockDim.x;
    for (int k = i; k < n_deg; k += stride) deg[k] = 0;
    for (int k = i; k < n_pool; k += stride) pooled[k] = 0.f;
}

// ---------------- degree count over dst ----------------
__global__ void deg_kernel(const int* __restrict__ dst, int* __restrict__ deg, int E) {
    int i = blockIdx.x * blockDim.x + threadIdx.x;
    if (i < E) atomicAdd(&deg[dst[i]], 1);
}

__global__ void dinv_kernel(const int* __restrict__ deg, float* __restrict__ dinv, int n) {
    int i = blockIdx.x * blockDim.x + threadIdx.x;
    if (i < n) dinv[i] = rsqrtf((float)deg[i] + 1.0f);
}

// ---------------- SGEMM: h = A @ W, agg = h*dinv^2 + b (fused epilogue) ------
// A: [M,K], W: [K,128]. BM=64, BN=128, BK=32, 256 threads, 8x4 per thread.
#define BM 64
#define BN 128
#define BK 32
__global__ __launch_bounds__(256) void gemm_kernel(
    const float* __restrict__ A, const float* __restrict__ W,
    const float* __restrict__ bias, const float* __restrict__ dinv,
    float* __restrict__ h, float* __restrict__ agg, int M, int K)
{
    __shared__ float As[BM][BK];
    __shared__ float Ws[BK][BN];
    int tx = threadIdx.x;
    int row0 = blockIdx.x * BM;
    int warp = tx >> 5, lane = tx & 31;
    int trow = warp * 8;     // 8 rows per thread
    int tcol = lane * 4;     // 4 cols per thread

    float acc[8][4];
#pragma unroll
    for (int i = 0; i < 8; i++)
#pragma unroll
        for (int j = 0; j < 4; j++) acc[i][j] = 0.f;

    for (int k0 = 0; k0 < K; k0 += BK) {
        // load A tile (coalesced rows of 128B)
#pragma unroll
        for (int i = tx; i < BM * BK; i += 256) {
            int r = i / BK, c = i % BK;
            int gr = row0 + r;
            As[r][c] = (gr < M) ? A[(size_t)gr * K + k0 + c] : 0.f;
        }
        // load W tile
#pragma unroll
        for (int i = tx; i < BK * BN; i += 256) {
            int r = i / BN, c = i % BN;
            Ws[r][c] = W[(size_t)(k0 + r) * BN + c];
        }
        __syncthreads();
#pragma unroll
        for (int k = 0; k < BK; k++) {
            float4 wv = *(const float4*)&Ws[k][tcol];
#pragma unroll
            for (int i = 0; i < 8; i++) {
                float a = As[trow + i][k];
                acc[i][0] += a * wv.x;
                acc[i][1] += a * wv.y;
                acc[i][2] += a * wv.z;
                acc[i][3] += a * wv.w;
            }
        }
        __syncthreads();
    }
    // epilogue: write h and agg = h*dinv^2 + bias
    float4 bv = *(const float4*)&bias[tcol];
#pragma unroll
    for (int i = 0; i < 8; i++) {
        int gr = row0 + trow + i;
        if (gr < M) {
            float dv = dinv[gr];
            float d2 = dv * dv;
            float4 hv = make_float4(acc[i][0], acc[i][1], acc[i][2], acc[i][3]);
            *(float4*)&h[(size_t)gr * CDIM + tcol] = hv;
            float4 av = make_float4(hv.x * d2 + bv.x, hv.y * d2 + bv.y,
                                    hv.z * d2 + bv.z, hv.w * d2 + bv.w);
            *(float4*)&agg[(size_t)gr * CDIM + tcol] = av;
        }
    }
}

// ---------------- edge scatter: agg[dst] += coef * h[src] -------------------
// one warp per edge, each lane does a float4 (32*4 = 128 channels)
__global__ __launch_bounds__(256) void edge_kernel(
    const int* __restrict__ src, const int* __restrict__ dst,
    const float* __restrict__ dinv, const float* __restrict__ h,
    float* __restrict__ agg, int E)
{
    int lane = threadIdx.x & 31;
    int gw = (blockIdx.x * blockDim.x + threadIdx.x) >> 5;
    int nw = (gridDim.x * blockDim.x) >> 5;
    for (int e = gw; e < E; e += nw) {
        int s = __ldg(&src[e]);
        int d = __ldg(&dst[e]);
        float coef = __ldg(&dinv[s]) * __ldg(&dinv[d]);
        float4 v = *(const float4*)(h + (size_t)s * CDIM + lane * 4);
        float* p = agg + (size_t)d * CDIM + lane * 4;
        asm volatile("red.global.add.v4.f32 [%0], {%1,%2,%3,%4};"
                     :: "l"(p), "f"(v.x * coef), "f"(v.y * coef),
                        "f"(v.z * coef), "f"(v.w * coef)
                     : "memory");
    }
}

// ---------------- relu + residual accumulate --------------------------------
__global__ void relu_acc_kernel(const float* __restrict__ agg, float* __restrict__ nxt,
                                float* __restrict__ s, int n4, int first)
{
    int i = blockIdx.x * blockDim.x + threadIdx.x;
    if (i >= n4) return;
    float4 a = ((const float4*)agg)[i];
    float4 r = make_float4(fmaxf(a.x, 0.f), fmaxf(a.y, 0.f),
                           fmaxf(a.z, 0.f), fmaxf(a.w, 0.f));
    ((float4*)nxt)[i] = r;
    if (first) {
        ((float4*)s)[i] = r;
    } else {
        float4 sv = ((float4*)s)[i];
        sv.x += r.x; sv.y += r.y; sv.z += r.z; sv.w += r.w;
        ((float4*)s)[i] = sv;
    }
}

// ---------------- masked pool: pooled[b,c] = sum_n mask[b,n]*s[b,n,c] --------
#define POOL_CHUNK 500
__global__ __launch_bounds__(128) void pool_kernel(
    const float* __restrict__ s, const int* __restrict__ mask,
    float* __restrict__ pooled)
{
    int b = blockIdx.y;
    int c = threadIdx.x;              // 0..127
    int n0 = blockIdx.x * POOL_CHUNK;
    int n1 = n0 + POOL_CHUNK;
    if (n1 > NPROT) n1 = NPROT;
    float acc = 0.f;
    for (int n = n0; n < n1; n++) {
        int m = __ldg(&mask[b * NPROT + n]);
        if (m) acc += s[((size_t)(b * NPROT + n)) * CDIM + c];
    }
    atomicAdd(&pooled[b * CDIM + c], acc);
}

// ---------------- tiny MLP: 128 -> 256 -> 64 -> 16 -> 1 ---------------------
__global__ __launch_bounds__(256) void mlp_kernel(
    const float* __restrict__ pooled,
    const float* __restrict__ lw1, const float* __restrict__ lb1,
    const float* __restrict__ lw2, const float* __restrict__ lb2,
    const float* __restrict__ lw3, const float* __restrict__ lb3,
    const float* __restrict__ lw4, const float* __restrict__ lb4,
    float* __restrict__ out)
{
    __shared__ float sp[BATCH * 128];
    __shared__ float z1[BATCH * 256];
    __shared__ float z2[BATCH * 64];
    __shared__ float z3[BATCH * 16];
    int tx = threadIdx.x;

    for (int i = tx; i < BATCH * 128; i += 256) sp[i] = pooled[i];
    __syncthreads();

    // layer 1: [4,128] @ [128,256]
    for (int i = tx; i < BATCH * 256; i += 256) {
        int b = i >> 8, c = i & 255;
        float acc = lb1[c];
        for (int k = 0; k < 128; k++) acc += sp[b * 128 + k] * lw1[k * 256 + c];
        z1[i] = fmaxf(acc, 0.f);
    }
    __syncthreads();

    // layer 2: [4,256] @ [256,64]
    for (int i = tx; i < BATCH * 64; i += 256) {
        int b = i >> 6, c = i & 63;
        float acc = lb2[c];
        for (int k = 0; k < 256; k++) acc += z1[b * 256 + k] * lw2[k * 64 + c];
        z2[i] = fmaxf(acc, 0.f);
    }
    __syncthreads();

    // layer 3: [4,64] @ [64,16]
    if (tx < BATCH * 16) {
        int b = tx >> 4, c = tx & 15;
        float acc = lb3[c];
        for (int k = 0; k < 64; k++) acc += z2[b * 64 + k] * lw3[k * 16 + c];
        z3[tx] = fmaxf(acc, 0.f);
    }
    __syncthreads();

    // layer 4: [4,16] @ [16,1]
    if (tx < BATCH) {
        float acc = lb4[0];
        for (int k = 0; k < 16; k++) acc += z3[tx * 16 + k] * lw4[k];
        out[tx] = acc;
    }
}

// ---------------- launch ----------------------------------------------------
extern "C" void kernel_launch(void* const* d_in, const int* in_sizes, int n_in,
                              void* d_out, int out_size)
{
    const float* x    = (const float*)d_in[0];
    const int*   eidx = (const int*)d_in[1];
    const int*   mask = (const int*)d_in[2];
    const float* W1 = (const float*)d_in[3];  const float* b1 = (const float*)d_in[4];
    const float* W2 = (const float*)d_in[5];  const float* b2 = (const float*)d_in[6];
    const float* W3 = (const float*)d_in[7];  const float* b3 = (const float*)d_in[8];
    const float* lw1 = (const float*)d_in[9];  const float* lb1 = (const float*)d_in[10];
    const float* lw2 = (const float*)d_in[11]; const float* lb2 = (const float*)d_in[12];
    const float* lw3 = (const float*)d_in[13]; const float* lb3 = (const float*)d_in[14];
    const float* lw4 = (const float*)d_in[15]; const float* lb4 = (const float*)d_in[16];
    float* out = (float*)d_out;

    int M = NODES;
    int E = in_sizes[1] / 2;
    const int* src = eidx;
    const int* dst = eidx + E;

    void *p_deg, *p_dinv, *p_h, *p_agg, *p_in, *p_s, *p_pool;
    cudaGetSymbolAddress(&p_deg, g_deg);
    cudaGetSymbolAddress(&p_dinv, g_dinv);
    cudaGetSymbolAddress(&p_h, g_h);
    cudaGetSymbolAddress(&p_agg, g_agg);
    cudaGetSymbolAddress(&p_in, g_in);
    cudaGetSymbolAddress(&p_s, g_s);
    cudaGetSymbolAddress(&p_pool, g_pooled);
    int*   deg  = (int*)p_deg;
    float* dinv = (float*)p_dinv;
    float* h    = (float*)p_h;
    float* agg  = (float*)p_agg;
    float* in   = (float*)p_in;
    float* s    = (float*)p_s;
    float* pool = (float*)p_pool;

    // 1. zero deg + pooled
    zero_kernel<<<256, 256>>>(deg, pool, M, BATCH * CDIM);
    // 2. degree
    deg_kernel<<<(E + 255) / 256, 256>>>(dst, deg, E);
    // 3. dinv
    dinv_kernel<<<(M + 255) / 256, 256>>>(deg, dinv, M);

    int n4 = M * CDIM / 4;
    int edge_blocks = 2368;   // 148 SMs * 16, grid-stride over warps

    // layer 1 (K=256)
    gemm_kernel<<<(M + BM - 1) / BM, 256>>>(x, W1, b1, dinv, h, agg, M, 256);
    edge_kernel<<<edge_blocks, 256>>>(src, dst, dinv, h, agg, E);
    relu_acc_kernel<<<(n4 + 255) / 256, 256>>>(agg, in, s, n4, 1);

    // layer 2 (K=128)
    gemm_kernel<<<(M + BM - 1) / BM, 256>>>(in, W2, b2, dinv, h, agg, M, 128);
    edge_kernel<<<edge_blocks, 256>>>(src, dst, dinv, h, agg, E);
    relu_acc_kernel<<<(n4 + 255) / 256, 256>>>(agg, in, s, n4, 0);

    // layer 3 (K=128)
    gemm_kernel<<<(M + BM - 1) / BM, 256>>>(in, W3, b3, dinv, h, agg, M, 128);
    edge_kernel<<<edge_blocks, 256>>>(src, dst, dinv, h, agg, E);
    relu_acc_kernel<<<(n4 + 255) / 256, 256>>>(agg, in, s, n4, 0);

    // pool
    dim3 pgrid((NPROT + POOL_CHUNK - 1) / POOL_CHUNK, BATCH);
    pool_kernel<<<pgrid, 128>>>(s, mask, pool);

    // MLP head
    mlp_kernel<<<1, 256>>>(pool, lw1, lb1, lw2, lb2, lw3, lb3, lw4, lb4, out);
}

// round 2
// speedup vs baseline: 1.2019x; 1.2019x over previous
#include <cuda_runtime.h>
#include <cuda_bf16.h>
#include <cstdint>

#define NODES   68000
#define BATCH   4
#define NPROT   17000
#define CDIM    128
#define EMAX    2200000

// ---------------- scratch (allocation-free: __device__ globals) ----------------
__device__ __align__(16) int   g_deg[NODES];
__device__ __align__(16) int   g_ptr[NODES + 1];
__device__ __align__(16) int   g_cursor[NODES];
__device__ __align__(16) int   g_csr[EMAX];
__device__ __align__(16) float g_dinv[NODES];
__device__ __align__(16) float g_hs[NODES * CDIM];     // hs = dinv * (in @ W)
__device__ __align__(16) float g_in[NODES * CDIM];     // next-layer input (relu output)
__device__ __align__(16) float g_s[NODES * CDIM];      // residual sum h1+h2+h3
__device__ __align__(16) float g_pooled[BATCH * CDIM];

// ---------------- zero init (deg + pooled) ----------------
__global__ void zero_kernel(int* deg, float* pooled, int n_deg, int n_pool) {
    int i = blockIdx.x * blockDim.x + threadIdx.x;
    int stride = gridDim.x * blockDim.x;
    for (int k = i; k < n_deg; k += stride) deg[k] = 0;
    for (int k = i; k < n_pool; k += stride) pooled[k] = 0.f;
}

// ---------------- degree count over dst ----------------
__global__ void deg_kernel(const int* __restrict__ dst, int* __restrict__ deg, int E) {
    int i = blockIdx.x * blockDim.x + threadIdx.x;
    if (i < E) atomicAdd(&deg[dst[i]], 1);
}

__global__ void dinv_kernel(const int* __restrict__ deg, float* __restrict__ dinv, int n) {
    int i = blockIdx.x * blockDim.x + threadIdx.x;
    if (i < n) dinv[i] = rsqrtf((float)deg[i] + 1.0f);
}

// ---------------- single-block exclusive scan of deg -> ptr, cursor ----------
#define SCAN_T 1024
__global__ __launch_bounds__(SCAN_T) void scan_kernel(
    const int* __restrict__ deg, int* __restrict__ ptr, int* __restrict__ cursor)
{
    __shared__ int part[SCAN_T];
    int t = threadIdx.x;
    const int chunk = (NODES + SCAN_T - 1) / SCAN_T;
    int lo = t * chunk;
    int hi = lo + chunk; if (hi > NODES) hi = NODES;
    int sum = 0;
    for (int i = lo; i < hi; i++) sum += deg[i];
    part[t] = sum;
    __syncthreads();
    // inclusive Hillis-Steele scan
    for (int off = 1; off < SCAN_T; off <<= 1) {
        int v = 0;
        if (t >= off) v = part[t - off];
        __syncthreads();
        if (t >= off) part[t] += v;
        __syncthreads();
    }
    int run = (t == 0) ? 0 : part[t - 1];
    for (int i = lo; i < hi; i++) {
        ptr[i] = run;
        cursor[i] = run;
        run += deg[i];
    }
    if (t == SCAN_T - 1) ptr[NODES] = part[SCAN_T - 1];
}

// ---------------- CSR build: scatter src ids into per-dst rows ---------------
__global__ void build_csr_kernel(const int* __restrict__ src, const int* __restrict__ dst,
                                 int* __restrict__ cursor, int* __restrict__ csr, int E)
{
    int i = blockIdx.x * blockDim.x + threadIdx.x;
    if (i < E) {
        int d = dst[i];
        int pos = atomicAdd(&cursor[d], 1);
        csr[pos] = src[i];
    }
}

// ---------------- SGEMM: hs = dinv * (A @ W) --------------------------------
// A: [M,K], W: [K,128]. BM=64, BN=128, BK=32, 256 threads, 8x4 per thread.
#define BM 64
#define BN 128
#define BK 32
__global__ __launch_bounds__(256, 2) void gemm_kernel(
    const float* __restrict__ A, const float* __restrict__ W,
    const float* __restrict__ dinv, float* __restrict__ hs, int M, int K)
{
    __shared__ float As[BM][BK];
    __shared__ float Ws[BK][BN];
    int tx = threadIdx.x;
    int row0 = blockIdx.x * BM;
    int warp = tx >> 5, lane = tx & 31;
    int trow = warp * 8;     // 8 rows per thread
    int tcol = lane * 4;     // 4 cols per thread

    float acc[8][4];
#pragma unroll
    for (int i = 0; i < 8; i++)
#pragma unroll
        for (int j = 0; j < 4; j++) acc[i][j] = 0.f;

    for (int k0 = 0; k0 < K; k0 += BK) {
        // load A tile: 64 rows x 32 cols, float4 per thread (BM*BK/4 = 512 f4)
#pragma unroll
        for (int i = tx; i < BM * BK / 4; i += 256) {
            int r = i / (BK / 4), c = (i % (BK / 4)) * 4;
            int gr = row0 + r;
            float4 v = make_float4(0.f, 0.f, 0.f, 0.f);
            if (gr < M) v = *(const float4*)&A[(size_t)gr * K + k0 + c];
            *(float4*)&As[r][c] = v;
        }
        // load W tile: 32 rows x 128 cols (BK*BN/4 = 1024 f4)
#pragma unroll
        for (int i = tx; i < BK * BN / 4; i += 256) {
            int r = i / (BN / 4), c = (i % (BN / 4)) * 4;
            *(float4*)&Ws[r][c] = *(const float4*)&W[(size_t)(k0 + r) * BN + c];
        }
        __syncthreads();
#pragma unroll
        for (int k = 0; k < BK; k += 4) {
            float4 wv0 = *(const float4*)&Ws[k + 0][tcol];
            float4 wv1 = *(const float4*)&Ws[k + 1][tcol];
            float4 wv2 = *(const float4*)&Ws[k + 2][tcol];
            float4 wv3 = *(const float4*)&Ws[k + 3][tcol];
#pragma unroll
            for (int i = 0; i < 8; i++) {
                float4 a = *(const float4*)&As[trow + i][k];
                acc[i][0] += a.x * wv0.x; acc[i][1] += a.x * wv0.y;
                acc[i][2] += a.x * wv0.z; acc[i][3] += a.x * wv0.w;
                acc[i][0] += a.y * wv1.x; acc[i][1] += a.y * wv1.y;
                acc[i][2] += a.y * wv1.z; acc[i][3] += a.y * wv1.w;
                acc[i][0] += a.z * wv2.x; acc[i][1] += a.z * wv2.y;
                acc[i][2] += a.z * wv2.z; acc[i][3] += a.z * wv2.w;
                acc[i][0] += a.w * wv3.x; acc[i][1] += a.w * wv3.y;
                acc[i][2] += a.w * wv3.z; acc[i][3] += a.w * wv3.w;
            }
        }
        __syncthreads();
    }
    // epilogue: hs = dinv * acc
#pragma unroll
    for (int i = 0; i < 8; i++) {
        int gr = row0 + trow + i;
        if (gr < M) {
            float dv = dinv[gr];
            float4 hv = make_float4(acc[i][0] * dv, acc[i][1] * dv,
                                    acc[i][2] * dv, acc[i][3] * dv);
            *(float4*)&hs[(size_t)gr * CDIM + tcol] = hv;
        }
    }
}

// ---------------- aggregation: warp per dst node, no atomics -----------------
// agg[n] = dinv[n] * (sum_{e in csr row n} hs[src_e] + hs[n]) + bias
// then relu, write next-layer input and residual sum.
__global__ __launch_bounds__(256) void agg_kernel(
    const int* __restrict__ ptr, const int* __restrict__ csr,
    const float* __restrict__ dinv, const float* __restrict__ hs,
    const float* __restrict__ bias, float* __restrict__ nxt,
    float* __restrict__ s, int first)
{
    int lane = threadIdx.x & 31;
    int node = (blockIdx.x * blockDim.x + threadIdx.x) >> 5;
    if (node >= NODES) return;

    int beg = __ldg(&ptr[node]);
    int end = __ldg(&ptr[node + 1]);
    int co = lane * 4;

    // self term (hs[node] = dinv[node]*h[node]; final scale by dinv[node] gives dinv^2*h)
    float4 acc = *(const float4*)&hs[(size_t)node * CDIM + co];

    int e = beg;
    for (; e + 4 <= end; e += 4) {
        int s0 = __ldg(&csr[e + 0]);
        int s1 = __ldg(&csr[e + 1]);
        int s2 = __ldg(&csr[e + 2]);
        int s3 = __ldg(&csr[e + 3]);
        float4 v0 = *(const float4*)&hs[(size_t)s0 * CDIM + co];
        float4 v1 = *(const float4*)&hs[(size_t)s1 * CDIM + co];
        float4 v2 = *(const float4*)&hs[(size_t)s2 * CDIM + co];
        float4 v3 = *(const float4*)&hs[(size_t)s3 * CDIM + co];
        acc.x += v0.x + v1.x + v2.x + v3.x;
        acc.y += v0.y + v1.y + v2.y + v3.y;
        acc.z += v0.z + v1.z + v2.z + v3.z;
        acc.w += v0.w + v1.w + v2.w + v3.w;
    }
    for (; e < end; e++) {
        int si = __ldg(&csr[e]);
        float4 v = *(const float4*)&hs[(size_t)si * CDIM + co];
        acc.x += v.x; acc.y += v.y; acc.z += v.z; acc.w += v.w;
    }

    float dv = dinv[node];
    float4 b4 = *(const float4*)&bias[co];
    float4 r = make_float4(fmaxf(acc.x * dv + b4.x, 0.f),
                           fmaxf(acc.y * dv + b4.y, 0.f),
                           fmaxf(acc.z * dv + b4.z, 0.f),
                           fmaxf(acc.w * dv + b4.w, 0.f));
    *(float4*)&nxt[(size_t)node * CDIM + co] = r;
    float* sp = s + (size_t)node * CDIM + co;
    if (first) {
        *(float4*)sp = r;
    } else {
        float4 sv = *(const float4*)sp;
        sv.x += r.x; sv.y += r.y; sv.z += r.z; sv.w += r.w;
        *(float4*)sp = sv;
    }
}

// ---------------- masked pool: pooled[b,c] = sum_n mask[b,n]*s[b,n,c] --------
#define POOL_CHUNK 500
__global__ __launch_bounds__(128) void pool_kernel(
    const float* __restrict__ s, const int* __restrict__ mask,
    float* __restrict__ pooled)
{
    int b = blockIdx.y;
    int c = threadIdx.x;              // 0..127
    int n0 = blockIdx.x * POOL_CHUNK;
    int n1 = n0 + POOL_CHUNK;
    if (n1 > NPROT) n1 = NPROT;
    float acc = 0.f;
    for (int n = n0; n < n1; n++) {
        int m = __ldg(&mask[b * NPROT + n]);
        if (m) acc += s[((size_t)(b * NPROT + n)) * CDIM + c];
    }
    atomicAdd(&pooled[b * CDIM + c], acc);
}

// ---------------- tiny MLP: 128 -> 256 -> 64 -> 16 -> 1 ---------------------
__global__ __launch_bounds__(256) void mlp_kernel(
    const float* __restrict__ pooled,
    const float* __restrict__ lw1, const float* __restrict__ lb1,
    const float* __restrict__ lw2, const float* __restrict__ lb2,
    const float* __restrict__ lw3, const float* __restrict__ lb3,
    const float* __restrict__ lw4, const float* __restrict__ lb4,
    float* __restrict__ out)
{
    __shared__ float sp[BATCH * 128];
    __shared__ float z1[BATCH * 256];
    __shared__ float z2[BATCH * 64];
    __shared__ float z3[BATCH * 16];
    int tx = threadIdx.x;

    for (int i = tx; i < BATCH * 128; i += 256) sp[i] = pooled[i];
    __syncthreads();

    for (int i = tx; i < BATCH * 256; i += 256) {
        int b = i >> 8, c = i & 255;
        float acc = lb1[c];
        for (int k = 0; k < 128; k++) acc += sp[b * 128 + k] * lw1[k * 256 + c];
        z1[i] = fmaxf(acc, 0.f);
    }
    __syncthreads();

    for (int i = tx; i < BATCH * 64; i += 256) {
        int b = i >> 6, c = i & 63;
        float acc = lb2[c];
        for (int k = 0; k < 256; k++) acc += z1[b * 256 + k] * lw2[k * 64 + c];
        z2[i] = fmaxf(acc, 0.f);
    }
    __syncthreads();

    if (tx < BATCH * 16) {
        int b = tx >> 4, c = tx & 15;
        float acc = lb3[c];
        for (int k = 0; k < 64; k++) acc += z2[b * 64 + k] * lw3[k * 16 + c];
        z3[tx] = fmaxf(acc, 0.f);
    }
    __syncthreads();

    if (tx < BATCH) {
        float acc = lb4[0];
        for (int k = 0; k < 16; k++) acc += z3[tx * 16 + k] * lw4[k];
        out[tx] = acc;
    }
}

// ---------------- launch ----------------------------------------------------
extern "C" void kernel_launch(void* const* d_in, const int* in_sizes, int n_in,
                              void* d_out, int out_size)
{
    const float* x    = (const float*)d_in[0];
    const int*   eidx = (const int*)d_in[1];
    const int*   mask = (const int*)d_in[2];
    const float* W1 = (const float*)d_in[3];  const float* b1 = (const float*)d_in[4];
    const float* W2 = (const float*)d_in[5];  const float* b2 = (const float*)d_in[6];
    const float* W3 = (const float*)d_in[7];  const float* b3 = (const float*)d_in[8];
    const float* lw1 = (const float*)d_in[9];  const float* lb1 = (const float*)d_in[10];
    const float* lw2 = (const float*)d_in[11]; const float* lb2 = (const float*)d_in[12];
    const float* lw3 = (const float*)d_in[13]; const float* lb3 = (const float*)d_in[14];
    const float* lw4 = (const float*)d_in[15]; const float* lb4 = (const float*)d_in[16];
    float* out = (float*)d_out;

    int M = NODES;
    int E = in_sizes[1] / 2;
    const int* src = eidx;
    const int* dst = eidx + E;

    void *p_deg, *p_ptr, *p_cur, *p_csr, *p_dinv, *p_hs, *p_in, *p_s, *p_pool;
    cudaGetSymbolAddress(&p_deg, g_deg);
    cudaGetSymbolAddress(&p_ptr, g_ptr);
    cudaGetSymbolAddress(&p_cur, g_cursor);
    cudaGetSymbolAddress(&p_csr, g_csr);
    cudaGetSymbolAddress(&p_dinv, g_dinv);
    cudaGetSymbolAddress(&p_hs, g_hs);
    cudaGetSymbolAddress(&p_in, g_in);
    cudaGetSymbolAddress(&p_s, g_s);
    cudaGetSymbolAddress(&p_pool, g_pooled);
    int*   deg  = (int*)p_deg;
    int*   ptr  = (int*)p_ptr;
    int*   cur  = (int*)p_cur;
    int*   csr  = (int*)p_csr;
    float* dinv = (float*)p_dinv;
    float* hs   = (float*)p_hs;
    float* in   = (float*)p_in;
    float* s    = (float*)p_s;
    float* pool = (float*)p_pool;

    // graph preprocessing
    zero_kernel<<<256, 256>>>(deg, pool, M, BATCH * CDIM);
    deg_kernel<<<(E + 255) / 256, 256>>>(dst, deg, E);
    dinv_kernel<<<(M + 255) / 256, 256>>>(deg, dinv, M);
    scan_kernel<<<1, SCAN_T>>>(deg, ptr, cur);
    build_csr_kernel<<<(E + 255) / 256, 256>>>(src, dst, cur, csr, E);

    int agg_blocks = (M * 32 + 255) / 256;   // warp per node

    // layer 1 (K=256)
    gemm_kernel<<<(M + BM - 1) / BM, 256>>>(x, W1, dinv, hs, M, 256);
    agg_kernel<<<agg_blocks, 256>>>(ptr, csr, dinv, hs, b1, in, s, 1);

    // layer 2 (K=128)
    gemm_kernel<<<(M + BM - 1) / BM, 256>>>(in, W2, dinv, hs, M, 128);
    agg_kernel<<<agg_blocks, 256>>>(ptr, csr, dinv, hs, b2, in, s, 0);

    // layer 3 (K=128)
    gemm_kernel<<<(M + BM - 1) / BM, 256>>>(in, W3, dinv, hs, M, 128);
    agg_kernel<<<agg_blocks, 256>>>(ptr, csr, dinv, hs, b3, in, s, 0);

    // pool
    dim3 pgrid((NPROT + POOL_CHUNK - 1) / POOL_CHUNK, BATCH);
    pool_kernel<<<pgrid, 128>>>(s, mask, pool);

    // MLP head
    mlp_kernel<<<1, 256>>>(pool, lw1, lb1, lw2, lb2, lw3, lb3, lw4, lb4, out);
}

// round 3
// speedup vs baseline: 1.9247x; 1.6014x over previous
#include <cuda_runtime.h>
#include <cuda_bf16.h>
#include <cstdint>

#define NODES   68000
#define BATCH   4
#define NPROT   17000
#define CDIM    128
#define EMAX    2200000

#define SCAN_BLOCKS  64
#define SCAN_THREADS 256
#define SCAN_TOTAL   (SCAN_BLOCKS * SCAN_THREADS)   // 16384 threads
#define SCAN_CHUNK   ((NODES + SCAN_TOTAL - 1) / SCAN_TOTAL)  // 5

// ---------------- scratch (allocation-free: __device__ globals) ----------------
__device__ __align__(16) int   g_deg[NODES];
__device__ __align__(16) int   g_ptr[NODES + 1];
__device__ __align__(16) int   g_cursor[NODES];
__device__ __align__(16) int   g_csr[EMAX];
__device__ __align__(16) int   g_tpart[SCAN_TOTAL];
__device__ __align__(16) float g_dinv[NODES];
__device__ __align__(16) float g_hs[NODES * CDIM];     // hs = dinv * (in @ W)
__device__ __align__(16) float g_in[NODES * CDIM];     // next-layer input (relu output)
__device__ __align__(16) float g_s[NODES * CDIM];      // residual sum h1+h2+h3
__device__ __align__(16) float g_pooled[BATCH * CDIM];

// ---------------- zero init (deg + pooled) ----------------
__global__ void zero_kernel(int* deg, float* pooled, int n_deg, int n_pool) {
    int i = blockIdx.x * blockDim.x + threadIdx.x;
    int stride = gridDim.x * blockDim.x;
    for (int k = i; k < n_deg; k += stride) deg[k] = 0;
    for (int k = i; k < n_pool; k += stride) pooled[k] = 0.f;
}

// ---------------- degree count over dst ----------------
__global__ void deg_kernel(const int* __restrict__ dst, int* __restrict__ deg, int E) {
    int i = blockIdx.x * blockDim.x + threadIdx.x;
    if (i < E) atomicAdd(&deg[dst[i]], 1);
}

__global__ void dinv_kernel(const int* __restrict__ deg, float* __restrict__ dinv, int n) {
    int i = blockIdx.x * blockDim.x + threadIdx.x;
    if (i < n) dinv[i] = rsqrtf((float)deg[i] + 1.0f);
}

// ---------------- multi-block scan of deg -> ptr, cursor ---------------------
// phase 1: per-thread chunk sums
__global__ __launch_bounds__(SCAN_THREADS) void scan_p1_kernel(
    const int* __restrict__ deg, int* __restrict__ tpart)
{
    int t = blockIdx.x * blockDim.x + threadIdx.x;
    int lo = t * SCAN_CHUNK;
    int hi = lo + SCAN_CHUNK; if (hi > NODES) hi = NODES;
    int sum = 0;
    for (int i = lo; i < hi; i++) sum += deg[i];
    tpart[t] = sum;
}

// phase 2: single block scans the 16384 partials -> exclusive prefixes in-place
#define P2_T 1024
#define P2_PER (SCAN_TOTAL / P2_T)   // 16
__global__ __launch_bounds__(P2_T) void scan_p2_kernel(int* __restrict__ tpart)
{
    __shared__ int bs[P2_T];
    int t = threadIdx.x;
    int v[P2_PER];
    int local = 0;
#pragma unroll
    for (int i = 0; i < P2_PER; i++) {
        v[i] = tpart[t * P2_PER + i];
        local += v[i];
    }
    bs[t] = local;
    __syncthreads();
    // Hillis-Steele inclusive scan over 1024 thread sums
    for (int off = 1; off < P2_T; off <<= 1) {
        int x = 0;
        if (t >= off) x = bs[t - off];
        __syncthreads();
        if (t >= off) bs[t] += x;
        __syncthreads();
    }
    int run = (t == 0) ? 0 : bs[t - 1];   // exclusive base for this thread's group
#pragma unroll
    for (int i = 0; i < P2_PER; i++) {
        tpart[t * P2_PER + i] = run;
        run += v[i];
    }
}

// phase 3: expand to per-node exclusive offsets
__global__ __launch_bounds__(SCAN_THREADS) void scan_p3_kernel(
    const int* __restrict__ deg, const int* __restrict__ tpart,
    int* __restrict__ ptr, int* __restrict__ cursor, int E)
{
    int t = blockIdx.x * blockDim.x + threadIdx.x;
    int lo = t * SCAN_CHUNK;
    int hi = lo + SCAN_CHUNK; if (hi > NODES) hi = NODES;
    int run = tpart[t];
    for (int i = lo; i < hi; i++) {
        ptr[i] = run;
        cursor[i] = run;
        run += deg[i];
    }
    if (t == 0) ptr[NODES] = E;
}

// ---------------- CSR build: scatter src ids into per-dst rows ---------------
__global__ void build_csr_kernel(const int* __restrict__ src, const int* __restrict__ dst,
                                 int* __restrict__ cursor, int* __restrict__ csr, int E)
{
    int i = blockIdx.x * blockDim.x + threadIdx.x;
    if (i < E) {
        int d = dst[i];
        int pos = atomicAdd(&cursor[d], 1);
        csr[pos] = src[i];
    }
}

// ---------------- SGEMM: hs = dinv * (A @ W) --------------------------------
// A: [M,K], W: [K,128]. BM=64, BN=128, BK=32, 256 threads, 8x4 per thread.
#define BM 64
#define BN 128
#define BK 32
__global__ __launch_bounds__(256, 2) void gemm_kernel(
    const float* __restrict__ A, const float* __restrict__ W,
    const float* __restrict__ dinv, float* __restrict__ hs, int M, int K)
{
    __shared__ float As[BM][BK];
    __shared__ float Ws[BK][BN];
    int tx = threadIdx.x;
    int row0 = blockIdx.x * BM;
    int warp = tx >> 5, lane = tx & 31;
    int trow = warp * 8;     // 8 rows per thread
    int tcol = lane * 4;     // 4 cols per thread

    float acc[8][4];
#pragma unroll
    for (int i = 0; i < 8; i++)
#pragma unroll
        for (int j = 0; j < 4; j++) acc[i][j] = 0.f;

    for (int k0 = 0; k0 < K; k0 += BK) {
#pragma unroll
        for (int i = tx; i < BM * BK / 4; i += 256) {
            int r = i / (BK / 4), c = (i % (BK / 4)) * 4;
            int gr = row0 + r;
            float4 v = make_float4(0.f, 0.f, 0.f, 0.f);
            if (gr < M) v = *(const float4*)&A[(size_t)gr * K + k0 + c];
            *(float4*)&As[r][c] = v;
        }
#pragma unroll
        for (int i = tx; i < BK * BN / 4; i += 256) {
            int r = i / (BN / 4), c = (i % (BN / 4)) * 4;
            *(float4*)&Ws[r][c] = *(const float4*)&W[(size_t)(k0 + r) * BN + c];
        }
        __syncthreads();
#pragma unroll
        for (int k = 0; k < BK; k += 4) {
            float4 wv0 = *(const float4*)&Ws[k + 0][tcol];
            float4 wv1 = *(const float4*)&Ws[k + 1][tcol];
            float4 wv2 = *(const float4*)&Ws[k + 2][tcol];
            float4 wv3 = *(const float4*)&Ws[k + 3][tcol];
#pragma unroll
            for (int i = 0; i < 8; i++) {
                float4 a = *(const float4*)&As[trow + i][k];
                acc[i][0] += a.x * wv0.x; acc[i][1] += a.x * wv0.y;
                acc[i][2] += a.x * wv0.z; acc[i][3] += a.x * wv0.w;
                acc[i][0] += a.y * wv1.x; acc[i][1] += a.y * wv1.y;
                acc[i][2] += a.y * wv1.z; acc[i][3] += a.y * wv1.w;
                acc[i][0] += a.z * wv2.x; acc[i][1] += a.z * wv2.y;
                acc[i][2] += a.z * wv2.z; acc[i][3] += a.z * wv2.w;
                acc[i][0] += a.w * wv3.x; acc[i][1] += a.w * wv3.y;
                acc[i][2] += a.w * wv3.z; acc[i][3] += a.w * wv3.w;
            }
        }
        __syncthreads();
    }
#pragma unroll
    for (int i = 0; i < 8; i++) {
        int gr = row0 + trow + i;
        if (gr < M) {
            float dv = dinv[gr];
            float4 hv = make_float4(acc[i][0] * dv, acc[i][1] * dv,
                                    acc[i][2] * dv, acc[i][3] * dv);
            *(float4*)&hs[(size_t)gr * CDIM + tcol] = hv;
        }
    }
}

// ---------------- aggregation: warp per dst node, no atomics -----------------
__global__ __launch_bounds__(256) void agg_kernel(
    const int* __restrict__ ptr, const int* __restrict__ csr,
    const float* __restrict__ dinv, const float* __restrict__ hs,
    const float* __restrict__ bias, float* __restrict__ nxt,
    float* __restrict__ s, int first)
{
    int lane = threadIdx.x & 31;
    int node = (blockIdx.x * blockDim.x + threadIdx.x) >> 5;
    if (node >= NODES) return;

    int beg = __ldg(&ptr[node]);
    int end = __ldg(&ptr[node + 1]);
    int co = lane * 4;

    float4 acc = *(const float4*)&hs[(size_t)node * CDIM + co];

    int e = beg;
    for (; e + 4 <= end; e += 4) {
        int s0 = __ldg(&csr[e + 0]);
        int s1 = __ldg(&csr[e + 1]);
        int s2 = __ldg(&csr[e + 2]);
        int s3 = __ldg(&csr[e + 3]);
        float4 v0 = *(const float4*)&hs[(size_t)s0 * CDIM + co];
        float4 v1 = *(const float4*)&hs[(size_t)s1 * CDIM + co];
        float4 v2 = *(const float4*)&hs[(size_t)s2 * CDIM + co];
        float4 v3 = *(const float4*)&hs[(size_t)s3 * CDIM + co];
        acc.x += v0.x + v1.x + v2.x + v3.x;
        acc.y += v0.y + v1.y + v2.y + v3.y;
        acc.z += v0.z + v1.z + v2.z + v3.z;
        acc.w += v0.w + v1.w + v2.w + v3.w;
    }
    for (; e < end; e++) {
        int si = __ldg(&csr[e]);
        float4 v = *(const float4*)&hs[(size_t)si * CDIM + co];
        acc.x += v.x; acc.y += v.y; acc.z += v.z; acc.w += v.w;
    }

    float dv = dinv[node];
    float4 b4 = *(const float4*)&bias[co];
    float4 r = make_float4(fmaxf(acc.x * dv + b4.x, 0.f),
                           fmaxf(acc.y * dv + b4.y, 0.f),
                           fmaxf(acc.z * dv + b4.z, 0.f),
                           fmaxf(acc.w * dv + b4.w, 0.f));
    *(float4*)&nxt[(size_t)node * CDIM + co] = r;
    float* sp = s + (size_t)node * CDIM + co;
    if (first) {
        *(float4*)sp = r;
    } else {
        float4 sv = *(const float4*)sp;
        sv.x += r.x; sv.y += r.y; sv.z += r.z; sv.w += r.w;
        *(float4*)sp = sv;
    }
}

// ---------------- masked pool: pooled[b,c] = sum_n mask[b,n]*s[b,n,c] --------
#define POOL_CHUNK 500
__global__ __launch_bounds__(128) void pool_kernel(
    const float* __restrict__ s, const int* __restrict__ mask,
    float* __restrict__ pooled)
{
    int b = blockIdx.y;
    int c = threadIdx.x;              // 0..127
    int n0 = blockIdx.x * POOL_CHUNK;
    int n1 = n0 + POOL_CHUNK;
    if (n1 > NPROT) n1 = NPROT;
    float acc = 0.f;
    for (int n = n0; n < n1; n++) {
        int m = __ldg(&mask[b * NPROT + n]);
        if (m) acc += s[((size_t)(b * NPROT + n)) * CDIM + c];
    }
    atomicAdd(&pooled[b * CDIM + c], acc);
}

// ---------------- tiny MLP: 128 -> 256 -> 64 -> 16 -> 1 ---------------------
__global__ __launch_bounds__(256) void mlp_kernel(
    const float* __restrict__ pooled,
    const float* __restrict__ lw1, const float* __restrict__ lb1,
    const float* __restrict__ lw2, const float* __restrict__ lb2,
    const float* __restrict__ lw3, const float* __restrict__ lb3,
    const float* __restrict__ lw4, const float* __restrict__ lb4,
    float* __restrict__ out)
{
    __shared__ float sp[BATCH * 128];
    __shared__ float z1[BATCH * 256];
    __shared__ float z2[BATCH * 64];
    __shared__ float z3[BATCH * 16];
    int tx = threadIdx.x;

    for (int i = tx; i < BATCH * 128; i += 256) sp[i] = pooled[i];
    __syncthreads();

    for (int i = tx; i < BATCH * 256; i += 256) {
        int b = i >> 8, c = i & 255;
        float acc = lb1[c];
        for (int k = 0; k < 128; k++) acc += sp[b * 128 + k] * lw1[k * 256 + c];
        z1[i] = fmaxf(acc, 0.f);
    }
    __syncthreads();

    for (int i = tx; i < BATCH * 64; i += 256) {
        int b = i >> 6, c = i & 63;
        float acc = lb2[c];
        for (int k = 0; k < 256; k++) acc += z1[b * 256 + k] * lw2[k * 64 + c];
        z2[i] = fmaxf(acc, 0.f);
    }
    __syncthreads();

    if (tx < BATCH * 16) {
        int b = tx >> 4, c = tx & 15;
        float acc = lb3[c];
        for (int k = 0; k < 64; k++) acc += z2[b * 64 + k] * lw3[k * 16 + c];
        z3[tx] = fmaxf(acc, 0.f);
    }
    __syncthreads();

    if (tx < BATCH) {
        float acc = lb4[0];
        for (int k = 0; k < 16; k++) acc += z3[tx * 16 + k] * lw4[k];
        out[tx] = acc;
    }
}

// ---------------- launch ----------------------------------------------------
extern "C" void kernel_launch(void* const* d_in, const int* in_sizes, int n_in,
                              void* d_out, int out_size)
{
    const float* x    = (const float*)d_in[0];
    const int*   eidx = (const int*)d_in[1];
    const int*   mask = (const int*)d_in[2];
    const float* W1 = (const float*)d_in[3];  const float* b1 = (const float*)d_in[4];
    const float* W2 = (const float*)d_in[5];  const float* b2 = (const float*)d_in[6];
    const float* W3 = (const float*)d_in[7];  const float* b3 = (const float*)d_in[8];
    const float* lw1 = (const float*)d_in[9];  const float* lb1 = (const float*)d_in[10];
    const float* lw2 = (const float*)d_in[11]; const float* lb2 = (const float*)d_in[12];
    const float* lw3 = (const float*)d_in[13]; const float* lb3 = (const float*)d_in[14];
    const float* lw4 = (const float*)d_in[15]; const float* lb4 = (const float*)d_in[16];
    float* out = (float*)d_out;

    int M = NODES;
    int E = in_sizes[1] / 2;
    const int* src = eidx;
    const int* dst = eidx + E;

    void *p_deg, *p_ptr, *p_cur, *p_csr, *p_tp, *p_dinv, *p_hs, *p_in, *p_s, *p_pool;
    cudaGetSymbolAddress(&p_deg, g_deg);
    cudaGetSymbolAddress(&p_ptr, g_ptr);
    cudaGetSymbolAddress(&p_cur, g_cursor);
    cudaGetSymbolAddress(&p_csr, g_csr);
    cudaGetSymbolAddress(&p_tp, g_tpart);
    cudaGetSymbolAddress(&p_dinv, g_dinv);
    cudaGetSymbolAddress(&p_hs, g_hs);
    cudaGetSymbolAddress(&p_in, g_in);
    cudaGetSymbolAddress(&p_s, g_s);
    cudaGetSymbolAddress(&p_pool, g_pooled);
    int*   deg  = (int*)p_deg;
    int*   ptr  = (int*)p_ptr;
    int*   cur  = (int*)p_cur;
    int*   csr  = (int*)p_csr;
    int*   tp   = (int*)p_tp;
    float* dinv = (float*)p_dinv;
    float* hs   = (float*)p_hs;
    float* in   = (float*)p_in;
    float* s    = (float*)p_s;
    float* pool = (float*)p_pool;

    // graph preprocessing
    zero_kernel<<<256, 256>>>(deg, pool, M, BATCH * CDIM);
    deg_kernel<<<(E + 255) / 256, 256>>>(dst, deg, E);
    dinv_kernel<<<(M + 255) / 256, 256>>>(deg, dinv, M);
    scan_p1_kernel<<<SCAN_BLOCKS, SCAN_THREADS>>>(deg, tp);
    scan_p2_kernel<<<1, P2_T>>>(tp);
    scan_p3_kernel<<<SCAN_BLOCKS, SCAN_THREADS>>>(deg, tp, ptr, cur, E);
    build_csr_kernel<<<(E + 255) / 256, 256>>>(src, dst, cur, csr, E);

    int agg_blocks = (M * 32 + 255) / 256;   // warp per node

    // layer 1 (K=256)
    gemm_kernel<<<(M + BM - 1) / BM, 256>>>(x, W1, dinv, hs, M, 256);
    agg_kernel<<<agg_blocks, 256>>>(ptr, csr, dinv, hs, b1, in, s, 1);

    // layer 2 (K=128)
    gemm_kernel<<<(M + BM - 1) / BM, 256>>>(in, W2, dinv, hs, M, 128);
    agg_kernel<<<agg_blocks, 256>>>(ptr, csr, dinv, hs, b2, in, s, 0);

    // layer 3 (K=128)
    gemm_kernel<<<(M + BM - 1) / BM, 256>>>(in, W3, dinv, hs, M, 128);
    agg_kernel<<<agg_blocks, 256>>>(ptr, csr, dinv, hs, b3, in, s, 0);

    // pool
    dim3 pgrid((NPROT + POOL_CHUNK - 1) / POOL_CHUNK, BATCH);
    pool_kernel<<<pgrid, 128>>>(s, mask, pool);

    // MLP head
    mlp_kernel<<<1, 256>>>(pool, lw1, lb1, lw2, lb2, lw3, lb3, lw4, lb4, out);
}

// round 4
// speedup vs baseline: 2.2029x; 1.1446x over previous
#include <cuda_runtime.h>
#include <cuda_fp16.h>
#include <cstdint>

#define NODES   68000
#define BATCH   4
#define NPROT   17000
#define CDIM    128
#define EMAX    2200000

#define SCAN_BLOCKS  64
#define SCAN_THREADS 256
#define SCAN_TOTAL   (SCAN_BLOCKS * SCAN_THREADS)   // 16384 threads
#define SCAN_CHUNK   ((NODES + SCAN_TOTAL - 1) / SCAN_TOTAL)  // 5

// ---------------- scratch (allocation-free: __device__ globals) ----------------
__device__ __align__(16) int    g_deg[NODES];
__device__ __align__(16) int    g_ptr[NODES + 1];
__device__ __align__(16) int    g_cursor[NODES];
__device__ __align__(16) int    g_csr[EMAX];
__device__ __align__(16) int    g_tpart[SCAN_TOTAL];
__device__ __align__(16) float  g_dinv[NODES];
__device__ __align__(16) __half g_hs[NODES * CDIM];    // hs = dinv * (in @ W), fp16
__device__ __align__(16) float  g_in[NODES * CDIM];    // next-layer input (relu output)
__device__ __align__(16) float  g_s[NODES * CDIM];     // residual sum h1+h2+h3
__device__ __align__(16) float  g_pooled[BATCH * CDIM];

// ---------------- zero init (deg + pooled) ----------------
__global__ void zero_kernel(int* deg, float* pooled, int n_deg, int n_pool) {
    int i = blockIdx.x * blockDim.x + threadIdx.x;
    int stride = gridDim.x * blockDim.x;
    for (int k = i; k < n_deg; k += stride) deg[k] = 0;
    for (int k = i; k < n_pool; k += stride) pooled[k] = 0.f;
}

// ---------------- degree count over dst ----------------
__global__ void deg_kernel(const int* __restrict__ dst, int* __restrict__ deg, int E) {
    int i = blockIdx.x * blockDim.x + threadIdx.x;
    if (i < E) atomicAdd(&deg[dst[i]], 1);
}

__global__ void dinv_kernel(const int* __restrict__ deg, float* __restrict__ dinv, int n) {
    int i = blockIdx.x * blockDim.x + threadIdx.x;
    if (i < n) dinv[i] = rsqrtf((float)deg[i] + 1.0f);
}

// ---------------- multi-block scan of deg -> ptr, cursor ---------------------
__global__ __launch_bounds__(SCAN_THREADS) void scan_p1_kernel(
    const int* __restrict__ deg, int* __restrict__ tpart)
{
    int t = blockIdx.x * blockDim.x + threadIdx.x;
    int lo = t * SCAN_CHUNK;
    int hi = lo + SCAN_CHUNK; if (hi > NODES) hi = NODES;
    int sum = 0;
    for (int i = lo; i < hi; i++) sum += deg[i];
    tpart[t] = sum;
}

#define P2_T 1024
#define P2_PER (SCAN_TOTAL / P2_T)   // 16
__global__ __launch_bounds__(P2_T) void scan_p2_kernel(int* __restrict__ tpart)
{
    __shared__ int bs[P2_T];
    int t = threadIdx.x;
    int v[P2_PER];
    int local = 0;
#pragma unroll
    for (int i = 0; i < P2_PER; i++) {
        v[i] = tpart[t * P2_PER + i];
        local += v[i];
    }
    bs[t] = local;
    __syncthreads();
    for (int off = 1; off < P2_T; off <<= 1) {
        int x = 0;
        if (t >= off) x = bs[t - off];
        __syncthreads();
        if (t >= off) bs[t] += x;
        __syncthreads();
    }
    int run = (t == 0) ? 0 : bs[t - 1];
#pragma unroll
    for (int i = 0; i < P2_PER; i++) {
        tpart[t * P2_PER + i] = run;
        run += v[i];
    }
}

__global__ __launch_bounds__(SCAN_THREADS) void scan_p3_kernel(
    const int* __restrict__ deg, const int* __restrict__ tpart,
    int* __restrict__ ptr, int* __restrict__ cursor, int E)
{
    int t = blockIdx.x * blockDim.x + threadIdx.x;
    int lo = t * SCAN_CHUNK;
    int hi = lo + SCAN_CHUNK; if (hi > NODES) hi = NODES;
    int run = tpart[t];
    for (int i = lo; i < hi; i++) {
        ptr[i] = run;
        cursor[i] = run;
        run += deg[i];
    }
    if (t == 0) ptr[NODES] = E;
}

// ---------------- CSR build: scatter src ids into per-dst rows ---------------
__global__ void build_csr_kernel(const int* __restrict__ src, const int* __restrict__ dst,
                                 int* __restrict__ cursor, int* __restrict__ csr, int E)
{
    int i = blockIdx.x * blockDim.x + threadIdx.x;
    if (i < E) {
        int d = dst[i];
        int pos = atomicAdd(&cursor[d], 1);
        csr[pos] = src[i];
    }
}

// ---------------- SGEMM: hs = fp16( dinv * (A @ W) ) ------------------------
#define BM 64
#define BN 128
#define BK 32
__global__ __launch_bounds__(256, 2) void gemm_kernel(
    const float* __restrict__ A, const float* __restrict__ W,
    const float* __restrict__ dinv, __half* __restrict__ hs, int M, int K)
{
    __shared__ float As[BM][BK];
    __shared__ float Ws[BK][BN];
    int tx = threadIdx.x;
    int row0 = blockIdx.x * BM;
    int warp = tx >> 5, lane = tx & 31;
    int trow = warp * 8;     // 8 rows per thread
    int tcol = lane * 4;     // 4 cols per thread

    float acc[8][4];
#pragma unroll
    for (int i = 0; i < 8; i++)
#pragma unroll
        for (int j = 0; j < 4; j++) acc[i][j] = 0.f;

    for (int k0 = 0; k0 < K; k0 += BK) {
#pragma unroll
        for (int i = tx; i < BM * BK / 4; i += 256) {
            int r = i / (BK / 4), c = (i % (BK / 4)) * 4;
            int gr = row0 + r;
            float4 v = make_float4(0.f, 0.f, 0.f, 0.f);
            if (gr < M) v = *(const float4*)&A[(size_t)gr * K + k0 + c];
            *(float4*)&As[r][c] = v;
        }
#pragma unroll
        for (int i = tx; i < BK * BN / 4; i += 256) {
            int r = i / (BN / 4), c = (i % (BN / 4)) * 4;
            *(float4*)&Ws[r][c] = *(const float4*)&W[(size_t)(k0 + r) * BN + c];
        }
        __syncthreads();
#pragma unroll
        for (int k = 0; k < BK; k += 4) {
            float4 wv0 = *(const float4*)&Ws[k + 0][tcol];
            float4 wv1 = *(const float4*)&Ws[k + 1][tcol];
            float4 wv2 = *(const float4*)&Ws[k + 2][tcol];
            float4 wv3 = *(const float4*)&Ws[k + 3][tcol];
#pragma unroll
            for (int i = 0; i < 8; i++) {
                float4 a = *(const float4*)&As[trow + i][k];
                acc[i][0] += a.x * wv0.x; acc[i][1] += a.x * wv0.y;
                acc[i][2] += a.x * wv0.z; acc[i][3] += a.x * wv0.w;
                acc[i][0] += a.y * wv1.x; acc[i][1] += a.y * wv1.y;
                acc[i][2] += a.y * wv1.z; acc[i][3] += a.y * wv1.w;
                acc[i][0] += a.z * wv2.x; acc[i][1] += a.z * wv2.y;
                acc[i][2] += a.z * wv2.z; acc[i][3] += a.z * wv2.w;
                acc[i][0] += a.w * wv3.x; acc[i][1] += a.w * wv3.y;
                acc[i][2] += a.w * wv3.z; acc[i][3] += a.w * wv3.w;
            }
        }
        __syncthreads();
    }
    // epilogue: hs = fp16(dinv * acc), 4 halves (8B) per thread-row
#pragma unroll
    for (int i = 0; i < 8; i++) {
        int gr = row0 + trow + i;
        if (gr < M) {
            float dv = dinv[gr];
            __half2 p0 = __floats2half2_rn(acc[i][0] * dv, acc[i][1] * dv);
            __half2 p1 = __floats2half2_rn(acc[i][2] * dv, acc[i][3] * dv);
            uint2 r;
            r.x = *(unsigned int*)&p0;
            r.y = *(unsigned int*)&p1;
            *(uint2*)&hs[(size_t)gr * CDIM + tcol] = r;
        }
    }
}

// ---------------- aggregation: warp per dst node, fp16 gather, fp32 accum ----
__global__ __launch_bounds__(256) void agg_kernel(
    const int* __restrict__ ptr, const int* __restrict__ csr,
    const float* __restrict__ dinv, const __half* __restrict__ hs,
    const float* __restrict__ bias, float* __restrict__ nxt,
    float* __restrict__ s, int first)
{
    int lane = threadIdx.x & 31;
    int node = (blockIdx.x * blockDim.x + threadIdx.x) >> 5;
    if (node >= NODES) return;

    int beg = __ldg(&ptr[node]);
    int end = __ldg(&ptr[node + 1]);
    int co = lane * 4;

    float a0, a1, a2, a3;
    {   // self term (hs already scaled by dinv[node])
        uint2 r = *(const uint2*)(hs + (size_t)node * CDIM + co);
        __half2 h0 = *(__half2*)&r.x;
        __half2 h1 = *(__half2*)&r.y;
        float2 f0 = __half22float2(h0);
        float2 f1 = __half22float2(h1);
        a0 = f0.x; a1 = f0.y; a2 = f1.x; a3 = f1.y;
    }

    int e = beg;
    for (; e + 4 <= end; e += 4) {
        int s0 = __ldg(&csr[e + 0]);
        int s1 = __ldg(&csr[e + 1]);
        int s2 = __ldg(&csr[e + 2]);
        int s3 = __ldg(&csr[e + 3]);
        uint2 r0 = *(const uint2*)(hs + (size_t)s0 * CDIM + co);
        uint2 r1 = *(const uint2*)(hs + (size_t)s1 * CDIM + co);
        uint2 r2 = *(const uint2*)(hs + (size_t)s2 * CDIM + co);
        uint2 r3 = *(const uint2*)(hs + (size_t)s3 * CDIM + co);
        float2 f;
        f = __half22float2(*(__half2*)&r0.x); a0 += f.x; a1 += f.y;
        f = __half22float2(*(__half2*)&r0.y); a2 += f.x; a3 += f.y;
        f = __half22float2(*(__half2*)&r1.x); a0 += f.x; a1 += f.y;
        f = __half22float2(*(__half2*)&r1.y); a2 += f.x; a3 += f.y;
        f = __half22float2(*(__half2*)&r2.x); a0 += f.x; a1 += f.y;
        f = __half22float2(*(__half2*)&r2.y); a2 += f.x; a3 += f.y;
        f = __half22float2(*(__half2*)&r3.x); a0 += f.x; a1 += f.y;
        f = __half22float2(*(__half2*)&r3.y); a2 += f.x; a3 += f.y;
    }
    for (; e < end; e++) {
        int si = __ldg(&csr[e]);
        uint2 r = *(const uint2*)(hs + (size_t)si * CDIM + co);
        float2 f;
        f = __half22float2(*(__half2*)&r.x); a0 += f.x; a1 += f.y;
        f = __half22float2(*(__half2*)&r.y); a2 += f.x; a3 += f.y;
    }

    float dv = dinv[node];
    float4 b4 = *(const float4*)&bias[co];
    float4 r = make_float4(fmaxf(a0 * dv + b4.x, 0.f),
                           fmaxf(a1 * dv + b4.y, 0.f),
                           fmaxf(a2 * dv + b4.z, 0.f),
                           fmaxf(a3 * dv + b4.w, 0.f));
    *(float4*)&nxt[(size_t)node * CDIM + co] = r;
    float* sp = s + (size_t)node * CDIM + co;
    if (first) {
        *(float4*)sp = r;
    } else {
        float4 sv = *(const float4*)sp;
        sv.x += r.x; sv.y += r.y; sv.z += r.z; sv.w += r.w;
        *(float4*)sp = sv;
    }
}

// ---------------- masked pool: pooled[b,c] = sum_n mask[b,n]*s[b,n,c] --------
#define POOL_CHUNK 500
__global__ __launch_bounds__(128) void pool_kernel(
    const float* __restrict__ s, const int* __restrict__ mask,
    float* __restrict__ pooled)
{
    int b = blockIdx.y;
    int c = threadIdx.x;              // 0..127
    int n0 = blockIdx.x * POOL_CHUNK;
    int n1 = n0 + POOL_CHUNK;
    if (n1 > NPROT) n1 = NPROT;
    float acc = 0.f;
    for (int n = n0; n < n1; n++) {
        int m = __ldg(&mask[b * NPROT + n]);
        if (m) acc += s[((size_t)(b * NPROT + n)) * CDIM + c];
    }
    atomicAdd(&pooled[b * CDIM + c], acc);
}

// ---------------- tiny MLP: 128 -> 256 -> 64 -> 16 -> 1 ---------------------
__global__ __launch_bounds__(256) void mlp_kernel(
    const float* __restrict__ pooled,
    const float* __restrict__ lw1, const float* __restrict__ lb1,
    const float* __restrict__ lw2, const float* __restrict__ lb2,
    const float* __restrict__ lw3, const float* __restrict__ lb3,
    const float* __restrict__ lw4, const float* __restrict__ lb4,
    float* __restrict__ out)
{
    __shared__ float sp[BATCH * 128];
    __shared__ float z1[BATCH * 256];
    __shared__ float z2[BATCH * 64];
    __shared__ float z3[BATCH * 16];
    int tx = threadIdx.x;

    for (int i = tx; i < BATCH * 128; i += 256) sp[i] = pooled[i];
    __syncthreads();

    for (int i = tx; i < BATCH * 256; i += 256) {
        int b = i >> 8, c = i & 255;
        float acc = lb1[c];
        for (int k = 0; k < 128; k++) acc += sp[b * 128 + k] * lw1[k * 256 + c];
        z1[i] = fmaxf(acc, 0.f);
    }
    __syncthreads();

    for (int i = tx; i < BATCH * 64; i += 256) {
        int b = i >> 6, c = i & 63;
        float acc = lb2[c];
        for (int k = 0; k < 256; k++) acc += z1[b * 256 + k] * lw2[k * 64 + c];
        z2[i] = fmaxf(acc, 0.f);
    }
    __syncthreads();

    if (tx < BATCH * 16) {
        int b = tx >> 4, c = tx & 15;
        float acc = lb3[c];
        for (int k = 0; k < 64; k++) acc += z2[b * 64 + k] * lw3[k * 16 + c];
        z3[tx] = fmaxf(acc, 0.f);
    }
    __syncthreads();

    if (tx < BATCH) {
        float acc = lb4[0];
        for (int k = 0; k < 16; k++) acc += z3[tx * 16 + k] * lw4[k];
        out[tx] = acc;
    }
}

// ---------------- launch ----------------------------------------------------
extern "C" void kernel_launch(void* const* d_in, const int* in_sizes, int n_in,
                              void* d_out, int out_size)
{
    const float* x    = (const float*)d_in[0];
    const int*   eidx = (const int*)d_in[1];
    const int*   mask = (const int*)d_in[2];
    const float* W1 = (const float*)d_in[3];  const float* b1 = (const float*)d_in[4];
    const float* W2 = (const float*)d_in[5];  const float* b2 = (const float*)d_in[6];
    const float* W3 = (const float*)d_in[7];  const float* b3 = (const float*)d_in[8];
    const float* lw1 = (const float*)d_in[9];  const float* lb1 = (const float*)d_in[10];
    const float* lw2 = (const float*)d_in[11]; const float* lb2 = (const float*)d_in[12];
    const float* lw3 = (const float*)d_in[13]; const float* lb3 = (const float*)d_in[14];
    const float* lw4 = (const float*)d_in[15]; const float* lb4 = (const float*)d_in[16];
    float* out = (float*)d_out;

    int M = NODES;
    int E = in_sizes[1] / 2;
    const int* src = eidx;
    const int* dst = eidx + E;

    void *p_deg, *p_ptr, *p_cur, *p_csr, *p_tp, *p_dinv, *p_hs, *p_in, *p_s, *p_pool;
    cudaGetSymbolAddress(&p_deg, g_deg);
    cudaGetSymbolAddress(&p_ptr, g_ptr);
    cudaGetSymbolAddress(&p_cur, g_cursor);
    cudaGetSymbolAddress(&p_csr, g_csr);
    cudaGetSymbolAddress(&p_tp, g_tpart);
    cudaGetSymbolAddress(&p_dinv, g_dinv);
    cudaGetSymbolAddress(&p_hs, g_hs);
    cudaGetSymbolAddress(&p_in, g_in);
    cudaGetSymbolAddress(&p_s, g_s);
    cudaGetSymbolAddress(&p_pool, g_pooled);
    int*    deg  = (int*)p_deg;
    int*    ptr  = (int*)p_ptr;
    int*    cur  = (int*)p_cur;
    int*    csr  = (int*)p_csr;
    int*    tp   = (int*)p_tp;
    float*  dinv = (float*)p_dinv;
    __half* hs   = (__half*)p_hs;
    float*  in   = (float*)p_in;
    float*  s    = (float*)p_s;
    float*  pool = (float*)p_pool;

    // graph preprocessing
    zero_kernel<<<256, 256>>>(deg, pool, M, BATCH * CDIM);
    deg_kernel<<<(E + 255) / 256, 256>>>(dst, deg, E);
    dinv_kernel<<<(M + 255) / 256, 256>>>(deg, dinv, M);
    scan_p1_kernel<<<SCAN_BLOCKS, SCAN_THREADS>>>(deg, tp);
    scan_p2_kernel<<<1, P2_T>>>(tp);
    scan_p3_kernel<<<SCAN_BLOCKS, SCAN_THREADS>>>(deg, tp, ptr, cur, E);
    build_csr_kernel<<<(E + 255) / 256, 256>>>(src, dst, cur, csr, E);

    int agg_blocks = (M * 32 + 255) / 256;   // warp per node

    // layer 1 (K=256)
    gemm_kernel<<<(M + BM - 1) / BM, 256>>>(x, W1, dinv, hs, M, 256);
    agg_kernel<<<agg_blocks, 256>>>(ptr, csr, dinv, hs, b1, in, s, 1);

    // layer 2 (K=128)
    gemm_kernel<<<(M + BM - 1) / BM, 256>>>(in, W2, dinv, hs, M, 128);
    agg_kernel<<<agg_blocks, 256>>>(ptr, csr, dinv, hs, b2, in, s, 0);

    // layer 3 (K=128)
    gemm_kernel<<<(M + BM - 1) / BM, 256>>>(in, W3, dinv, hs, M, 128);
    agg_kernel<<<agg_blocks, 256>>>(ptr, csr, dinv, hs, b3, in, s, 0);

    // pool
    dim3 pgrid((NPROT + POOL_CHUNK - 1) / POOL_CHUNK, BATCH);
    pool_kernel<<<pgrid, 128>>>(s, mask, pool);

    // MLP head
    mlp_kernel<<<1, 256>>>(pool, lw1, lb1, lw2, lb2, lw3, lb3, lw4, lb4, out);
}

// round 5
// speedup vs baseline: 2.8997x; 1.3163x over previous
#include <cuda_runtime.h>
#include <cuda_fp16.h>
#include <mma.h>
#include <cstdint>

using namespace nvcuda;

#define NODES   68000
#define BATCH   4
#define NPROT   17000
#define CDIM    128
#define EMAX    2200000

#define SCAN_BLOCKS  64
#define SCAN_THREADS 256
#define SCAN_TOTAL   (SCAN_BLOCKS * SCAN_THREADS)
#define SCAN_CHUNK   ((NODES + SCAN_TOTAL - 1) / SCAN_TOTAL)

// ---------------- scratch (allocation-free: __device__ globals) ----------------
__device__ __align__(16) int    g_deg[NODES];
__device__ __align__(16) int    g_ptr[NODES + 1];
__device__ __align__(16) int    g_cursor[NODES];
__device__ __align__(16) int    g_csr[EMAX];
__device__ __align__(16) int    g_tpart[SCAN_TOTAL];
__device__ __align__(16) float  g_dinv[NODES];
__device__ __align__(16) __half g_xh[NODES * 256];     // fp16 copy of x
__device__ __align__(16) __half g_w1h[256 * CDIM];
__device__ __align__(16) __half g_w2h[CDIM * CDIM];
__device__ __align__(16) __half g_w3h[CDIM * CDIM];
__device__ __align__(16) __half g_hs[NODES * CDIM];    // hs = dinv * (in @ W), fp16
__device__ __align__(16) __half g_in[NODES * CDIM];    // next-layer input (fp16)
__device__ __align__(16) float  g_s[NODES * CDIM];     // residual sum h1+h2+h3
__device__ __align__(16) float  g_pooled[BATCH * CDIM];

// ---------------- fp32 -> fp16 conversion (n multiple of 4) ----------------
__global__ void f2h_kernel(const float* __restrict__ x, __half* __restrict__ xh, int n4) {
    int i = blockIdx.x * blockDim.x + threadIdx.x;
    int stride = gridDim.x * blockDim.x;
    for (int k = i; k < n4; k += stride) {
        float4 v = ((const float4*)x)[k];
        __half2 p0 = __floats2half2_rn(v.x, v.y);
        __half2 p1 = __floats2half2_rn(v.z, v.w);
        uint2 r;
        r.x = *(unsigned int*)&p0;
        r.y = *(unsigned int*)&p1;
        ((uint2*)xh)[k] = r;
    }
}

// ---------------- zero init ----------------
__global__ void zero_kernel(int* deg, float* pooled, int n_deg, int n_pool) {
    int i = blockIdx.x * blockDim.x + threadIdx.x;
    int stride = gridDim.x * blockDim.x;
    for (int k = i; k < n_deg; k += stride) deg[k] = 0;
    for (int k = i; k < n_pool; k += stride) pooled[k] = 0.f;
}

__global__ void deg_kernel(const int* __restrict__ dst, int* __restrict__ deg, int E) {
    int i = blockIdx.x * blockDim.x + threadIdx.x;
    if (i < E) atomicAdd(&deg[dst[i]], 1);
}

__global__ void dinv_kernel(const int* __restrict__ deg, float* __restrict__ dinv, int n) {
    int i = blockIdx.x * blockDim.x + threadIdx.x;
    if (i < n) dinv[i] = rsqrtf((float)deg[i] + 1.0f);
}

// ---------------- multi-block scan ----------------
__global__ __launch_bounds__(SCAN_THREADS) void scan_p1_kernel(
    const int* __restrict__ deg, int* __restrict__ tpart)
{
    int t = blockIdx.x * blockDim.x + threadIdx.x;
    int lo = t * SCAN_CHUNK;
    int hi = lo + SCAN_CHUNK; if (hi > NODES) hi = NODES;
    int sum = 0;
    for (int i = lo; i < hi; i++) sum += deg[i];
    tpart[t] = sum;
}

#define P2_T 1024
#define P2_PER (SCAN_TOTAL / P2_T)
__global__ __launch_bounds__(P2_T) void scan_p2_kernel(int* __restrict__ tpart)
{
    __shared__ int bs[P2_T];
    int t = threadIdx.x;
    int v[P2_PER];
    int local = 0;
#pragma unroll
    for (int i = 0; i < P2_PER; i++) {
        v[i] = tpart[t * P2_PER + i];
        local += v[i];
    }
    bs[t] = local;
    __syncthreads();
    for (int off = 1; off < P2_T; off <<= 1) {
        int x = 0;
        if (t >= off) x = bs[t - off];
        __syncthreads();
        if (t >= off) bs[t] += x;
        __syncthreads();
    }
    int run = (t == 0) ? 0 : bs[t - 1];
#pragma unroll
    for (int i = 0; i < P2_PER; i++) {
        tpart[t * P2_PER + i] = run;
        run += v[i];
    }
}

__global__ __launch_bounds__(SCAN_THREADS) void scan_p3_kernel(
    const int* __restrict__ deg, const int* __restrict__ tpart,
    int* __restrict__ ptr, int* __restrict__ cursor, int E)
{
    int t = blockIdx.x * blockDim.x + threadIdx.x;
    int lo = t * SCAN_CHUNK;
    int hi = lo + SCAN_CHUNK; if (hi > NODES) hi = NODES;
    int run = tpart[t];
    for (int i = lo; i < hi; i++) {
        ptr[i] = run;
        cursor[i] = run;
        run += deg[i];
    }
    if (t == 0) ptr[NODES] = E;
}

__global__ void build_csr_kernel(const int* __restrict__ src, const int* __restrict__ dst,
                                 int* __restrict__ cursor, int* __restrict__ csr, int E)
{
    int i = blockIdx.x * blockDim.x + threadIdx.x;
    if (i < E) {
        int d = dst[i];
        int pos = atomicAdd(&cursor[d], 1);
        csr[pos] = src[i];
    }
}

// ---------------- HGEMM (wmma): hs = fp16( dinv * (A @ W) ) ------------------
// A: [M,K] fp16, W: [K,128] fp16. Block tile 128x128, BK=32, 8 warps (32x64 each).
#define GBM 128
#define GBK 32
#define LDA 40     // GBK + 8 halves
#define LDB 136    // CDIM + 8 halves
#define LDC 132    // CDIM + 4 floats
#define SM_AS 0
#define SM_BS (GBM * LDA * 2)                    // 10240
#define SM_CS (SM_BS + GBK * LDB * 2)            // 18944
#define SM_TOTAL (SM_CS + GBM * LDC * 4)         // 86528

__global__ __launch_bounds__(256) void hgemm_kernel(
    const __half* __restrict__ A, const __half* __restrict__ W,
    const float* __restrict__ dinv, __half* __restrict__ hs, int M, int K)
{
    extern __shared__ char smem[];
    __half* As = (__half*)(smem + SM_AS);
    __half* Bs = (__half*)(smem + SM_BS);
    float*  Cs = (float*)(smem + SM_CS);

    int tx = threadIdx.x;
    int row0 = blockIdx.x * GBM;
    int warp = tx >> 5;
    int wr = warp & 3;          // 4 row groups of 32
    int wc = warp >> 2;         // 2 col groups of 64

    wmma::fragment<wmma::accumulator, 16, 16, 16, float> acc[2][4];
#pragma unroll
    for (int mi = 0; mi < 2; mi++)
#pragma unroll
        for (int ni = 0; ni < 4; ni++) wmma::fill_fragment(acc[mi][ni], 0.f);

    for (int k0 = 0; k0 < K; k0 += GBK) {
        // load A tile: 128 x 32 halves (512 float4 loads)
#pragma unroll
        for (int i = tx; i < GBM * GBK / 8; i += 256) {
            int r = i >> 2, c8 = (i & 3) * 8;
            int gr = row0 + r;
            float4 v = make_float4(0.f, 0.f, 0.f, 0.f);
            if (gr < M) v = *(const float4*)&A[(size_t)gr * K + k0 + c8];
            *(float4*)&As[r * LDA + c8] = v;
        }
        // load B tile: 32 x 128 halves (512 float4 loads)
#pragma unroll
        for (int i = tx; i < GBK * CDIM / 8; i += 256) {
            int r = i >> 4, c8 = (i & 15) * 8;
            *(float4*)&Bs[r * LDB + c8] = *(const float4*)&W[(size_t)(k0 + r) * CDIM + c8];
        }
        __syncthreads();
#pragma unroll
        for (int ks = 0; ks < GBK; ks += 16) {
            wmma::fragment<wmma::matrix_a, 16, 16, 16, __half, wmma::row_major> af[2];
            wmma::fragment<wmma::matrix_b, 16, 16, 16, __half, wmma::row_major> bf[4];
#pragma unroll
            for (int mi = 0; mi < 2; mi++)
                wmma::load_matrix_sync(af[mi], &As[(wr * 32 + mi * 16) * LDA + ks], LDA);
#pragma unroll
            for (int ni = 0; ni < 4; ni++)
                wmma::load_matrix_sync(bf[ni], &Bs[ks * LDB + wc * 64 + ni * 16], LDB);
#pragma unroll
            for (int mi = 0; mi < 2; mi++)
#pragma unroll
                for (int ni = 0; ni < 4; ni++)
                    wmma::mma_sync(acc[mi][ni], af[mi], bf[ni], acc[mi][ni]);
        }
        __syncthreads();
    }

    // store accumulators to smem
#pragma unroll
    for (int mi = 0; mi < 2; mi++)
#pragma unroll
        for (int ni = 0; ni < 4; ni++)
            wmma::store_matrix_sync(&Cs[(wr * 32 + mi * 16) * LDC + wc * 64 + ni * 16],
                                    acc[mi][ni], LDC, wmma::mem_row_major);
    __syncthreads();

    // epilogue: hs = fp16(dinv * C)
    int col4 = (tx & 31) * 4;
    int rstart = tx >> 5;
    for (int r = rstart; r < GBM; r += 8) {
        int gr = row0 + r;
        if (gr < M) {
            float dv = dinv[gr];
            float c0 = Cs[r * LDC + col4 + 0] * dv;
            float c1 = Cs[r * LDC + col4 + 1] * dv;
            float c2 = Cs[r * LDC + col4 + 2] * dv;
            float c3 = Cs[r * LDC + col4 + 3] * dv;
            __half2 p0 = __floats2half2_rn(c0, c1);
            __half2 p1 = __floats2half2_rn(c2, c3);
            uint2 w;
            w.x = *(unsigned int*)&p0;
            w.y = *(unsigned int*)&p1;
            *(uint2*)&hs[(size_t)gr * CDIM + col4] = w;
        }
    }
}

// ---------------- aggregation: warp per dst node, fp16 gather ----------------
__global__ __launch_bounds__(256) void agg_kernel(
    const int* __restrict__ ptr, const int* __restrict__ csr,
    const float* __restrict__ dinv, const __half* __restrict__ hs,
    const float* __restrict__ bias, __half* __restrict__ nxt,
    float* __restrict__ s, int first)
{
    int lane = threadIdx.x & 31;
    int node = (blockIdx.x * blockDim.x + threadIdx.x) >> 5;
    if (node >= NODES) return;

    int beg = __ldg(&ptr[node]);
    int end = __ldg(&ptr[node + 1]);
    int co = lane * 4;

    float a0, a1, a2, a3;
    {
        uint2 r = *(const uint2*)(hs + (size_t)node * CDIM + co);
        float2 f0 = __half22float2(*(__half2*)&r.x);
        float2 f1 = __half22float2(*(__half2*)&r.y);
        a0 = f0.x; a1 = f0.y; a2 = f1.x; a3 = f1.y;
    }

    int e = beg;
    for (; e + 4 <= end; e += 4) {
        int s0 = __ldg(&csr[e + 0]);
        int s1 = __ldg(&csr[e + 1]);
        int s2 = __ldg(&csr[e + 2]);
        int s3 = __ldg(&csr[e + 3]);
        uint2 r0 = *(const uint2*)(hs + (size_t)s0 * CDIM + co);
        uint2 r1 = *(const uint2*)(hs + (size_t)s1 * CDIM + co);
        uint2 r2 = *(const uint2*)(hs + (size_t)s2 * CDIM + co);
        uint2 r3 = *(const uint2*)(hs + (size_t)s3 * CDIM + co);
        float2 f;
        f = __half22float2(*(__half2*)&r0.x); a0 += f.x; a1 += f.y;
        f = __half22float2(*(__half2*)&r0.y); a2 += f.x; a3 += f.y;
        f = __half22float2(*(__half2*)&r1.x); a0 += f.x; a1 += f.y;
        f = __half22float2(*(__half2*)&r1.y); a2 += f.x; a3 += f.y;
        f = __half22float2(*(__half2*)&r2.x); a0 += f.x; a1 += f.y;
        f = __half22float2(*(__half2*)&r2.y); a2 += f.x; a3 += f.y;
        f = __half22float2(*(__half2*)&r3.x); a0 += f.x; a1 += f.y;
        f = __half22float2(*(__half2*)&r3.y); a2 += f.x; a3 += f.y;
    }
    for (; e < end; e++) {
        int si = __ldg(&csr[e]);
        uint2 r = *(const uint2*)(hs + (size_t)si * CDIM + co);
        float2 f;
        f = __half22float2(*(__half2*)&r.x); a0 += f.x; a1 += f.y;
        f = __half22float2(*(__half2*)&r.y); a2 += f.x; a3 += f.y;
    }

    float dv = dinv[node];
    float4 b4 = *(const float4*)&bias[co];
    float r0 = fmaxf(a0 * dv + b4.x, 0.f);
    float r1 = fmaxf(a1 * dv + b4.y, 0.f);
    float r2 = fmaxf(a2 * dv + b4.z, 0.f);
    float r3 = fmaxf(a3 * dv + b4.w, 0.f);

    // next-layer input (fp16)
    __half2 p0 = __floats2half2_rn(r0, r1);
    __half2 p1 = __floats2half2_rn(r2, r3);
    uint2 w;
    w.x = *(unsigned int*)&p0;
    w.y = *(unsigned int*)&p1;
    *(uint2*)&nxt[(size_t)node * CDIM + co] = w;

    float* sp = s + (size_t)node * CDIM + co;
    if (first) {
        *(float4*)sp = make_float4(r0, r1, r2, r3);
    } else {
        float4 sv = *(const float4*)sp;
        sv.x += r0; sv.y += r1; sv.z += r2; sv.w += r3;
        *(float4*)sp = sv;
    }
}

// ---------------- masked pool ----------------
#define POOL_CHUNK 500
__global__ __launch_bounds__(128) void pool_kernel(
    const float* __restrict__ s, const int* __restrict__ mask,
    float* __restrict__ pooled)
{
    int b = blockIdx.y;
    int c = threadIdx.x;
    int n0 = blockIdx.x * POOL_CHUNK;
    int n1 = n0 + POOL_CHUNK;
    if (n1 > NPROT) n1 = NPROT;
    float acc = 0.f;
    for (int n = n0; n < n1; n++) {
        int m = __ldg(&mask[b * NPROT + n]);
        if (m) acc += s[((size_t)(b * NPROT + n)) * CDIM + c];
    }
    atomicAdd(&pooled[b * CDIM + c], acc);
}

// ---------------- tiny MLP ----------------
__global__ __launch_bounds__(256) void mlp_kernel(
    const float* __restrict__ pooled,
    const float* __restrict__ lw1, const float* __restrict__ lb1,
    const float* __restrict__ lw2, const float* __restrict__ lb2,
    const float* __restrict__ lw3, const float* __restrict__ lb3,
    const float* __restrict__ lw4, const float* __restrict__ lb4,
    float* __restrict__ out)
{
    __shared__ float sp[BATCH * 128];
    __shared__ float z1[BATCH * 256];
    __shared__ float z2[BATCH * 64];
    __shared__ float z3[BATCH * 16];
    int tx = threadIdx.x;

    for (int i = tx; i < BATCH * 128; i += 256) sp[i] = pooled[i];
    __syncthreads();

    for (int i = tx; i < BATCH * 256; i += 256) {
        int b = i >> 8, c = i & 255;
        float acc = lb1[c];
        for (int k = 0; k < 128; k++) acc += sp[b * 128 + k] * lw1[k * 256 + c];
        z1[i] = fmaxf(acc, 0.f);
    }
    __syncthreads();

    for (int i = tx; i < BATCH * 64; i += 256) {
        int b = i >> 6, c = i & 63;
        float acc = lb2[c];
        for (int k = 0; k < 256; k++) acc += z1[b * 256 + k] * lw2[k * 64 + c];
        z2[i] = fmaxf(acc, 0.f);
    }
    __syncthreads();

    if (tx < BATCH * 16) {
        int b = tx >> 4, c = tx & 15;
        float acc = lb3[c];
        for (int k = 0; k < 64; k++) acc += z2[b * 64 + k] * lw3[k * 16 + c];
        z3[tx] = fmaxf(acc, 0.f);
    }
    __syncthreads();

    if (tx < BATCH) {
        float acc = lb4[0];
        for (int k = 0; k < 16; k++) acc += z3[tx * 16 + k] * lw4[k];
        out[tx] = acc;
    }
}

// ---------------- launch ----------------
extern "C" void kernel_launch(void* const* d_in, const int* in_sizes, int n_in,
                              void* d_out, int out_size)
{
    const float* x    = (const float*)d_in[0];
    const int*   eidx = (const int*)d_in[1];
    const int*   mask = (const int*)d_in[2];
    const float* W1 = (const float*)d_in[3];  const float* b1 = (const float*)d_in[4];
    const float* W2 = (const float*)d_in[5];  const float* b2 = (const float*)d_in[6];
    const float* W3 = (const float*)d_in[7];  const float* b3 = (const float*)d_in[8];
    const float* lw1 = (const float*)d_in[9];  const float* lb1 = (const float*)d_in[10];
    const float* lw2 = (const float*)d_in[11]; const float* lb2 = (const float*)d_in[12];
    const float* lw3 = (const float*)d_in[13]; const float* lb3 = (const float*)d_in[14];
    const float* lw4 = (const float*)d_in[15]; const float* lb4 = (const float*)d_in[16];
    float* out = (float*)d_out;

    int M = NODES;
    int E = in_sizes[1] / 2;
    const int* src = eidx;
    const int* dst = eidx + E;

    void *p_deg, *p_ptr, *p_cur, *p_csr, *p_tp, *p_dinv, *p_hs, *p_in, *p_s, *p_pool;
    void *p_xh, *p_w1h, *p_w2h, *p_w3h;
    cudaGetSymbolAddress(&p_deg, g_deg);
    cudaGetSymbolAddress(&p_ptr, g_ptr);
    cudaGetSymbolAddress(&p_cur, g_cursor);
    cudaGetSymbolAddress(&p_csr, g_csr);
    cudaGetSymbolAddress(&p_tp, g_tpart);
    cudaGetSymbolAddress(&p_dinv, g_dinv);
    cudaGetSymbolAddress(&p_hs, g_hs);
    cudaGetSymbolAddress(&p_in, g_in);
    cudaGetSymbolAddress(&p_s, g_s);
    cudaGetSymbolAddress(&p_pool, g_pooled);
    cudaGetSymbolAddress(&p_xh, g_xh);
    cudaGetSymbolAddress(&p_w1h, g_w1h);
    cudaGetSymbolAddress(&p_w2h, g_w2h);
    cudaGetSymbolAddress(&p_w3h, g_w3h);
    int*    deg  = (int*)p_deg;
    int*    ptr  = (int*)p_ptr;
    int*    cur  = (int*)p_cur;
    int*    csr  = (int*)p_csr;
    int*    tp   = (int*)p_tp;
    float*  dinv = (float*)p_dinv;
    __half* hs   = (__half*)p_hs;
    __half* in   = (__half*)p_in;
    float*  s    = (float*)p_s;
    float*  pool = (float*)p_pool;
    __half* xh   = (__half*)p_xh;
    __half* w1h  = (__half*)p_w1h;
    __half* w2h  = (__half*)p_w2h;
    __half* w3h  = (__half*)p_w3h;

    cudaFuncSetAttribute(hgemm_kernel, cudaFuncAttributeMaxDynamicSharedMemorySize, SM_TOTAL);

    // conversions (independent of graph prep)
    f2h_kernel<<<1024, 256>>>(x, xh, M * 256 / 4);
    f2h_kernel<<<32, 256>>>(W1, w1h, 256 * CDIM / 4);
    f2h_kernel<<<16, 256>>>(W2, w2h, CDIM * CDIM / 4);
    f2h_kernel<<<16, 256>>>(W3, w3h, CDIM * CDIM / 4);

    // graph preprocessing
    zero_kernel<<<256, 256>>>(deg, pool, M, BATCH * CDIM);
    deg_kernel<<<(E + 255) / 256, 256>>>(dst, deg, E);
    dinv_kernel<<<(M + 255) / 256, 256>>>(deg, dinv, M);
    scan_p1_kernel<<<SCAN_BLOCKS, SCAN_THREADS>>>(deg, tp);
    scan_p2_kernel<<<1, P2_T>>>(tp);
    scan_p3_kernel<<<SCAN_BLOCKS, SCAN_THREADS>>>(deg, tp, ptr, cur, E);
    build_csr_kernel<<<(E + 255) / 256, 256>>>(src, dst, cur, csr, E);

    int agg_blocks = (M * 32 + 255) / 256;
    int gemm_blocks = (M + GBM - 1) / GBM;

    // layer 1 (K=256)
    hgemm_kernel<<<gemm_blocks, 256, SM_TOTAL>>>(xh, w1h, dinv, hs, M, 256);
    agg_kernel<<<agg_blocks, 256>>>(ptr, csr, dinv, hs, b1, in, s, 1);

    // layer 2 (K=128)
    hgemm_kernel<<<gemm_blocks, 256, SM_TOTAL>>>(in, w2h, dinv, hs, M, 128);
    agg_kernel<<<agg_blocks, 256>>>(ptr, csr, dinv, hs, b2, in, s, 0);

    // layer 3 (K=128)
    hgemm_kernel<<<gemm_blocks, 256, SM_TOTAL>>>(in, w3h, dinv, hs, M, 128);
    agg_kernel<<<agg_blocks, 256>>>(ptr, csr, dinv, hs, b3, in, s, 0);

    // pool
    dim3 pgrid((NPROT + POOL_CHUNK - 1) / POOL_CHUNK, BATCH);
    pool_kernel<<<pgrid, 128>>>(s, mask, pool);

    // MLP head
    mlp_kernel<<<1, 256>>>(pool, lw1, lb1, lw2, lb2, lw3, lb3, lw4, lb4, out);
}